// round 14
// baseline (speedup 1.0000x reference)
#include <cuda_runtime.h>
#include <cstdint>

// ===================== problem sizes =====================
#define TOKENS 8192      // B*S = 4*2048
#define HID    2048
#define IDIM   8192

// ===================== scratch (device globals) =====================
__device__ float g_Y  [TOKENS * HID];          // 64 MB  LN output (tf32, K-permuted)
__device__ float g_W1t[2 * IDIM * HID];        // 128 MB W1^T [16384][2048] (tf32, K-perm)
__device__ float g_W2t[HID * IDIM];            // 64 MB  W2^T [2048][8192]  (tf32, K-perm)
__device__ float g_Z  [TOKENS * IDIM];         // 256 MB GeGLU output (tf32, K-perm)

// ===================== helpers =====================
__device__ __forceinline__ uint32_t smem_u32(const void* p) {
    uint32_t a;
    asm("{ .reg .u64 t; cvta.to.shared.u64 t, %1; cvt.u32.u64 %0, t; }" : "=r"(a) : "l"(p));
    return a;
}
__device__ __forceinline__ float rna_tf32(float f) {
    uint32_t u;
    asm("cvt.rna.tf32.f32 %0, %1;" : "=r"(u) : "f"(f));
    return __uint_as_float(u);
}
__device__ __forceinline__ void cp_async16(uint32_t dst, const void* src) {
    asm volatile("cp.async.cg.shared.global [%0], [%1], 16;" :: "r"(dst), "l"(src) : "memory");
}
__device__ __forceinline__ void cp_commit() {
    asm volatile("cp.async.commit_group;" ::: "memory");
}
template <int N>
__device__ __forceinline__ void cp_wait() {
    asm volatile("cp.async.wait_group %0;" :: "n"(N) : "memory");
}
// K-permutation within each 32-float chunk: logical kk*8+j ->
//   j<4 : kk*8 + 2j ; j>=4: kk*8 + 2(j-4)+1   (pairs (k, k+4) adjacent)
__device__ __forceinline__ int perm32(int l32) {
    const int j = l32 & 7;
    return (l32 & 24) + ((j < 4) ? (j << 1) : (((j - 4) << 1) + 1));
}
__device__ __forceinline__ float gelu_tanh(float a) {
    return 0.5f * a * (1.0f + tanhf(0.7978845608028654f * (a + 0.044715f * a * a * a)));
}

// m16n8k8 tf32 MMA (fp32 acc); operands consumed directly, no repacking.
__device__ __forceinline__ void mma_tf32(float* c, uint2 a0, uint2 a1, uint2 b) {
    asm volatile(
        "mma.sync.aligned.m16n8k8.row.col.f32.tf32.tf32.f32 "
        "{%0,%1,%2,%3}, {%4,%5,%6,%7}, {%8,%9}, {%0,%1,%2,%3};"
        : "+f"(c[0]), "+f"(c[1]), "+f"(c[2]), "+f"(c[3])
        : "r"(a0.x), "r"(a1.x), "r"(a0.y), "r"(a1.y), "r"(b.x), "r"(b.y));
}

// ===================== LayerNorm -> g_Y (tf32, K-permuted) =====================
__global__ void __launch_bounds__(256) ln_kernel(const float* __restrict__ x,
                                                 const float* __restrict__ scale,
                                                 const float* __restrict__ bias) {
    __shared__ float red1[8], red2[8];
    const int row = blockIdx.x;
    const int tid = threadIdx.x, wid = tid >> 5, lid = tid & 31;
    const float* xr = x + (size_t)row * HID;

    float v[8];
#pragma unroll
    for (int i = 0; i < 8; i++) v[i] = xr[tid + i * 256];

    float s1 = 0.f, s2 = 0.f;
#pragma unroll
    for (int i = 0; i < 8; i++) { s1 += v[i]; s2 += v[i] * v[i]; }
#pragma unroll
    for (int o = 16; o > 0; o >>= 1) {
        s1 += __shfl_xor_sync(0xFFFFFFFF, s1, o);
        s2 += __shfl_xor_sync(0xFFFFFFFF, s2, o);
    }
    if (lid == 0) { red1[wid] = s1; red2[wid] = s2; }
    __syncthreads();
    if (tid == 0) {
        float t1 = 0.f, t2 = 0.f;
#pragma unroll
        for (int i = 0; i < 8; i++) { t1 += red1[i]; t2 += red2[i]; }
        red1[0] = t1; red2[0] = t2;
    }
    __syncthreads();
    const float mu  = red1[0] * (1.0f / HID);
    const float var = red2[0] * (1.0f / HID) - mu * mu;
    const float inv = rsqrtf(var + 1e-6f);

    float* yr = g_Y + (size_t)row * HID;
#pragma unroll
    for (int i = 0; i < 8; i++) {
        const int c = tid + i * 256;
        const int pc = (c & ~31) + perm32(c & 31);
        yr[pc] = rna_tf32((v[i] - mu) * inv * scale[c] + bias[c]);
    }
}

// ===================== transpose + tf32 round + K-perm =====================
__global__ void __launch_bounds__(256) transpose_kernel(const float* __restrict__ in,
                                                        float* __restrict__ out,
                                                        int R, int C) {
    __shared__ float t[32][33];
    const int bx = blockIdx.x, by = blockIdx.y;
    const int tx = threadIdx.x, ty = threadIdx.y;   // (32, 8)
    const int x = bx * 32 + tx;
#pragma unroll
    for (int j = 0; j < 32; j += 8)
        t[ty + j][tx] = in[(size_t)(by * 32 + ty + j) * C + x];
    __syncthreads();
    const int oxp = by * 32 + perm32(tx);
#pragma unroll
    for (int j = 0; j < 32; j += 8)
        out[(size_t)(bx * 32 + ty + j) * R + oxp] = rna_tf32(t[tx][ty + j]);
}

// ===================== tiled tf32 mma.sync GEMM =====================
// 256 threads, BM=128, BN=128, BK=32, 8 warps (4m x 2n), warp tile 32x64.
// XOR-swizzled 128B rows (no padding): 3 stages x 32 KB -> 2 CTAs/SM AND a
// single __syncthreads per K-iteration.
// MODE 0: B = [64 gelu rows | 64 linear rows]; fused GeGLU -> g_Z (64 cols/blk)
// MODE 1: g_Z * W2t -> d_out (128 cols/blk)
#define BM 128
#define BN 128
#define BK 32
#define ROW_BYTES 128
#define STAGE_ROWS (BM + BN)                   // 256
#define STAGE_BYTES (STAGE_ROWS * ROW_BYTES)   // 32768
#define STAGES 3
#define SMEM_NEED (STAGES * STAGE_BYTES)       // 98304

template <int MODE>
__global__ void __launch_bounds__(256, 2) gemm_kernel(float* __restrict__ outp) {
    constexpr int K  = (MODE == 0) ? HID : IDIM;
    constexpr int NC = K / BK;
    constexpr int numBn = (MODE == 0) ? (IDIM / 64) : (HID / BN);   // 128 / 16

    extern __shared__ float smem[];
    const uint32_t smaddr = smem_u32(smem);

    const int tid = threadIdx.x, wid = tid >> 5, lid = tid & 31;
    const int warp_m = wid & 3;        // 0..3 -> 32-row strip
    const int warp_n = wid >> 2;       // 0..1 -> 64-col strip
    const int g  = lid >> 2;           // 0..7
    const int tg = lid & 3;            // 0..3

    // supertile remap: groups of 8 m-tiles sweep bn together (L2 reuse)
    const int bid   = blockIdx.x;
    const int group = bid / (8 * numBn);
    const int rem   = bid % (8 * numBn);
    const int m0    = (group * 8 + (rem & 7)) * BM;
    const int bn    = rem / 8;

    int nB0, nB1;
    if (MODE == 0) { nB0 = bn * 64;  nB1 = IDIM + bn * 64; }
    else           { nB0 = bn * BN;  nB1 = nB0 + 64; }

    const float* __restrict__ A  = (MODE == 0) ? g_Y : g_Z;
    const float* __restrict__ Bw = (MODE == 0) ? g_W1t : g_W2t;

    // ---- producer state: 8 persistent gmem pointers + 8 fixed swizzled dsts
    const int ch = tid & 7;            // 16B chunk in row
    const int pr = tid >> 3;           // 0..31
    const uint32_t chsw = (uint32_t)((ch * 16) ^ ((pr & 7) << 4));  // swizzled chunk off
    const float* gp[8];
    uint32_t dst[8];
    {
        const float* Ag  = A  + (size_t)m0  * K + ch * 4;
        const float* B0g = Bw + (size_t)nB0 * K + ch * 4;
        const float* B1g = Bw + (size_t)nB1 * K + ch * 4;
#pragma unroll
        for (int j = 0; j < 4; ++j) {            // A rows pr + 32j
            gp[j]  = Ag + (size_t)(pr + 32 * j) * K;
            dst[j] = smaddr + (pr + 32 * j) * ROW_BYTES + chsw;
        }
#pragma unroll
        for (int j = 0; j < 2; ++j) {            // B0 local rows
            gp[4 + j]  = B0g + (size_t)(pr + 32 * j) * K;
            dst[4 + j] = smaddr + (128 + pr + 32 * j) * ROW_BYTES + chsw;
        }
#pragma unroll
        for (int j = 0; j < 2; ++j) {            // B1 local rows
            gp[6 + j]  = B1g + (size_t)(pr + 32 * j) * K;
            dst[6 + j] = smaddr + (192 + pr + 32 * j) * ROW_BYTES + chsw;
        }
    }
    uint32_t psoff = 0;                          // producer stage byte-offset
    auto issue_stage = [&]() {
#pragma unroll
        for (int j = 0; j < 8; ++j) {
            cp_async16(dst[j] + psoff, gp[j]);
            gp[j] += BK;
        }
        cp_commit();
        psoff = (psoff == 2 * STAGE_BYTES) ? 0 : psoff + STAGE_BYTES;
    };

    // ---- consumer fragment bases (swizzled thread-const in bits 3..6)
    const uint32_t fsw = (uint32_t)((tg * 8) ^ (g << 4));
    const char* abase = (const char*)smem + (warp_m * 32 + g & ~7) * ROW_BYTES;
    // NOTE: row base must exclude g (it's folded into fsw's XOR? no) — keep explicit:
    const char* a0 = (const char*)smem + (warp_m * 32 + g) * ROW_BYTES + (tg * 8 ^ (g << 4)) - (tg * 8 ^ (g << 4)) ;
    (void)abase; (void)a0; (void)fsw;
    const uintptr_t abase2 = (uintptr_t)smem + (uint32_t)((warp_m * 32 + g) * ROW_BYTES) + (uint32_t)((tg * 8) ^ (g << 4));
    const uintptr_t bbase2 = (uintptr_t)smem + (uint32_t)((tg * 8) ^ (g << 4)) +
        (uint32_t)(((MODE == 0) ? (128 + warp_n * 32 + g) : (128 + warp_n * 64 + g)) * ROW_BYTES);

    float acc[2][8][4];
#pragma unroll
    for (int mt = 0; mt < 2; ++mt)
#pragma unroll
        for (int nt = 0; nt < 8; ++nt)
#pragma unroll
            for (int q = 0; q < 4; ++q) acc[mt][nt][q] = 0.f;

    issue_stage();                               // stage 0
    issue_stage();                               // stage 1
    uint32_t csoff = 0;

    for (int c = 0; c < NC; ++c) {
        cp_wait<1>();
        __syncthreads();                         // single barrier per iter
        if (c + 2 < NC) issue_stage(); else cp_commit();

        const uintptr_t ai = abase2 + csoff;
        const uintptr_t bi = bbase2 + csoff;
        csoff = (csoff == 2 * STAGE_BYTES) ? 0 : csoff + STAGE_BYTES;

#pragma unroll
        for (int kk = 0; kk < 4; ++kk) {
            const uintptr_t kx = (uintptr_t)(kk * 32);   // bits 5..6 only
            uint2 au[2][2];
#pragma unroll
            for (int mt = 0; mt < 2; ++mt) {
                au[mt][0] = *(const uint2*)((ai + mt * 16 * ROW_BYTES) ^ kx);
                au[mt][1] = *(const uint2*)((ai + (mt * 16 + 8) * ROW_BYTES) ^ kx);
            }
            uint2 bu[8];
#pragma unroll
            for (int nt = 0; nt < 8; ++nt) {
                const int ntoff = (MODE == 0)
                    ? ((nt >> 2) * 64 + (nt & 3) * 8) * ROW_BYTES
                    : nt * 8 * ROW_BYTES;
                bu[nt] = *(const uint2*)((bi + ntoff) ^ kx);
            }
#pragma unroll
            for (int mt = 0; mt < 2; ++mt)
#pragma unroll
                for (int nt = 0; nt < 8; ++nt)
                    mma_tf32(acc[mt][nt], au[mt][0], au[mt][1], bu[nt]);
        }
    }

    // ---- epilogue ----
    if (MODE == 0) {
        // z = gelu(left) * right; stored K-permuted into g_Z (64 cols per block).
        const int pp = (tg & 1) * 4 + (tg >> 1);
#pragma unroll
        for (int mt = 0; mt < 2; ++mt) {
            const int r0 = m0 + warp_m * 32 + mt * 16 + g;
#pragma unroll
            for (int nt = 0; nt < 4; ++nt) {
                const int colb = bn * 64 + warp_n * 32 + nt * 8;
                const float* L = acc[mt][nt];       // gelu branch
                const float* R = acc[mt][nt + 4];   // linear branch
                float* z0 = g_Z + (size_t)r0 * IDIM + colb;
                float* z1 = g_Z + (size_t)(r0 + 8) * IDIM + colb;
                z0[pp]     = rna_tf32(gelu_tanh(L[0]) * R[0]);
                z0[pp + 2] = rna_tf32(gelu_tanh(L[1]) * R[1]);
                z1[pp]     = rna_tf32(gelu_tanh(L[2]) * R[2]);
                z1[pp + 2] = rna_tf32(gelu_tanh(L[3]) * R[3]);
            }
        }
    } else {
#pragma unroll
        for (int mt = 0; mt < 2; ++mt) {
            const int r0 = m0 + warp_m * 32 + mt * 16 + g;
#pragma unroll
            for (int nt = 0; nt < 8; ++nt) {
                const int col = nB0 + warp_n * 64 + nt * 8 + tg * 2;
                *(float2*)(outp + (size_t)r0 * HID + col) =
                    make_float2(acc[mt][nt][0], acc[mt][nt][1]);
                *(float2*)(outp + (size_t)(r0 + 8) * HID + col) =
                    make_float2(acc[mt][nt][2], acc[mt][nt][3]);
            }
        }
    }
}

// ===================== launch =====================
extern "C" void kernel_launch(void* const* d_in, const int* in_sizes, int n_in,
                              void* d_out, int out_size) {
    const float* x     = (const float*)d_in[0];
    const float* scale = (const float*)d_in[1];
    const float* bias  = (const float*)d_in[2];
    const float* k1    = (const float*)d_in[3];   // [2048][16384]
    const float* k2    = (const float*)d_in[4];   // [8192][2048]
    float* out = (float*)d_out;

    float* w1t; cudaGetSymbolAddress((void**)&w1t, g_W1t);
    float* w2t; cudaGetSymbolAddress((void**)&w2t, g_W2t);

    cudaFuncSetAttribute(gemm_kernel<0>, cudaFuncAttributeMaxDynamicSharedMemorySize, SMEM_NEED);
    cudaFuncSetAttribute(gemm_kernel<1>, cudaFuncAttributeMaxDynamicSharedMemorySize, SMEM_NEED);

    // 1) LayerNorm -> g_Y (K-permuted tf32)
    ln_kernel<<<TOKENS, 256>>>(x, scale, bias);

    // 2) W1 [2048][16384] -> g_W1t [16384][2048] (K-permuted tf32)
    transpose_kernel<<<dim3(2 * IDIM / 32, HID / 32), dim3(32, 8)>>>(k1, w1t, HID, 2 * IDIM);

    // 3) W2 [8192][2048] -> g_W2t [2048][8192] (K-permuted tf32)
    transpose_kernel<<<dim3(HID / 32, IDIM / 32), dim3(32, 8)>>>(k2, w2t, IDIM, HID);

    // 4) GEMM1 + fused GeGLU -> g_Z   (64 m-tiles x 128 z-col-tiles)
    gemm_kernel<0><<<64 * 128, 256, SMEM_NEED>>>(out);

    // 5) GEMM2 -> out                 (64 m-tiles x 16 n-tiles)
    gemm_kernel<1><<<64 * 16, 256, SMEM_NEED>>>(out);
}